// round 13
// baseline (speedup 1.0000x reference)
#include <cuda_runtime.h>
#include <cstdint>
#include <cfloat>

// Problem constants
#define F 4096      // nb_features
#define C 64        // coord dim
#define B 1024      // batch
#define K 16        // nb_neighbors
#define J (F*K + 1) // 65537 gathered columns

// Scratch (no allocations allowed; __device__ globals are the sanctioned path)
__device__ float g_sq[F];
__device__ int   g_cols[J];
__device__ float g_d2[(size_t)F * F];   // 64 MB distance-squared matrix (L2-resident)

__device__ __forceinline__ bool lexlt(float d, int g, float v, int i) {
    return (d < v) || (d == v && g < i);
}

__device__ __forceinline__ unsigned long long fma2p(unsigned long long a,
                                                    unsigned long long b,
                                                    unsigned long long c) {
    unsigned long long d;
    asm("fma.rn.f32x2 %0, %1, %2, %3;" : "=l"(d) : "l"(a), "l"(b), "l"(c));
    return d;
}
__device__ __forceinline__ float lo32(unsigned long long v) {
    return __uint_as_float((unsigned)v);
}
__device__ __forceinline__ float hi32(unsigned long long v) {
    return __uint_as_float((unsigned)(v >> 32));
}

// ---------------------------------------------------------------------------
// Kernel 1: per-feature squared norms (UNFUSED mul+add, sequential — matches
// the reference's square+reduce rounding; rel_err is exactly 0 with this).
// ---------------------------------------------------------------------------
__global__ __launch_bounds__(256) void k_sq(const float* __restrict__ coord) {
    int f = blockIdx.x * 256 + threadIdx.x;
    float s = 0.f;
#pragma unroll
    for (int c = 0; c < C; ++c) {
        float x = coord[c * F + f];
        s = __fadd_rn(s, __fmul_rn(x, x));
    }
    g_sq[f] = s;
}

// ---------------------------------------------------------------------------
// Kernel 2: PURE distance GEMM -> g_d2 (verified ~52us; FROZEN).
// ---------------------------------------------------------------------------
#define ROWS_CTA 32
#define GW       1024
#define TGG      128
#define NT       (GW / TGG)   // 8

__global__ __launch_bounds__(256) void k_dist(const float* __restrict__ coord) {
    __shared__ float s_f[C * ROWS_CTA];   // 8 KB
    __shared__ float s_sqf[ROWS_CTA];
    __shared__ float s_g[C * TGG];        // 32 KB
    __shared__ float s_sqg[TGG];

    const int tid  = threadIdx.x;
    const int lane = tid & 31;
    const int w    = tid >> 5;           // warp id: rows w*4 .. w*4+3
    const int f0   = (blockIdx.x >> 2) * ROWS_CTA;
    const int g0   = (blockIdx.x & 3) * GW;

    for (int idx = tid; idx < (C * ROWS_CTA) / 4; idx += 256) {
        int c = idx >> 3, r4 = (idx & 7) * 4;
        *(float4*)(s_f + c * ROWS_CTA + r4) = *(const float4*)(coord + c * F + f0 + r4);
    }
    if (tid < ROWS_CTA / 4)
        *(float4*)(s_sqf + tid * 4) = *(const float4*)(g_sq + f0 + tid * 4);

    for (int t = 0; t < NT; ++t) {
        const int gb = g0 + t * TGG;
        __syncthreads();
        for (int idx = tid; idx < (C * TGG) / 4; idx += 256) {
            int c = idx >> 5, o4 = (idx & 31) * 4;
            *(float4*)(s_g + c * TGG + o4) = *(const float4*)(coord + c * F + gb + o4);
        }
        if (tid < TGG / 4)
            *(float4*)(s_sqg + tid * 4) = *(const float4*)(g_sq + gb + tid * 4);
        __syncthreads();

        unsigned long long p00 = 0, p01 = 0, p10 = 0, p11 = 0;
        unsigned long long p20 = 0, p21 = 0, p30 = 0, p31 = 0;

        const float* fp = s_f + w * 4;
        const float* gp = s_g + lane * 4;
#pragma unroll 2
        for (int c = 0; c < C; ++c) {
            float4 a = *(const float4*)(fp + c * ROWS_CTA);            // 4 rows, bcast
            ulonglong2 bb = *(const ulonglong2*)(gp + c * TGG);        // g pairs
            unsigned long long ax, ay, az, aw;
            asm("mov.b64 %0,{%1,%1};" : "=l"(ax) : "r"(__float_as_uint(a.x)));
            asm("mov.b64 %0,{%1,%1};" : "=l"(ay) : "r"(__float_as_uint(a.y)));
            asm("mov.b64 %0,{%1,%1};" : "=l"(az) : "r"(__float_as_uint(a.z)));
            asm("mov.b64 %0,{%1,%1};" : "=l"(aw) : "r"(__float_as_uint(a.w)));
            p00 = fma2p(ax, bb.x, p00);  p01 = fma2p(ax, bb.y, p01);
            p10 = fma2p(ay, bb.x, p10);  p11 = fma2p(ay, bb.y, p11);
            p20 = fma2p(az, bb.x, p20);  p21 = fma2p(az, bb.y, p21);
            p30 = fma2p(aw, bb.x, p30);  p31 = fma2p(aw, bb.y, p31);
        }

        float4 sg = *(const float4*)(s_sqg + lane * 4);
        const float* sfp = s_sqf + w * 4;
        float* obase = g_d2 + (size_t)(f0 + w * 4) * F + gb + lane * 4;
#define FIN_ROW(PL, PH, R)                                                     \
        {                                                                      \
            float sf = sfp[R];                                                 \
            float4 d;                                                          \
            d.x = __fadd_rn(__fmaf_rn(-2.f, lo32(PL), sg.x), sf);              \
            d.y = __fadd_rn(__fmaf_rn(-2.f, hi32(PL), sg.y), sf);              \
            d.z = __fadd_rn(__fmaf_rn(-2.f, lo32(PH), sg.z), sf);              \
            d.w = __fadd_rn(__fmaf_rn(-2.f, hi32(PH), sg.w), sf);              \
            *(float4*)(obase + (size_t)(R) * F) = d;                           \
        }
        FIN_ROW(p00, p01, 0) FIN_ROW(p10, p11, 1)
        FIN_ROW(p20, p21, 2) FIN_ROW(p30, p31, 3)
#undef FIN_ROW
    }
}

// ---------------------------------------------------------------------------
// Kernel 3: per-row top-16 via CTA-wide QUATERNARY bisection (3 probes per
// iteration, counts packed in 10-bit fields of one redux) on the bit-monotone
// key of fmaxf(d2,0). Exact 16th key bracketing, +7 ulp sqrt-tie margin, smem
// compaction (order-free), exact (sqrt, idx) lex ranks in parallel.
// One CTA (256 threads) per row; float4 loads.
// ---------------------------------------------------------------------------
#define ELEMS   16              // F / 256
#define CANDMAX 128

__global__ __launch_bounds__(256) void k_select() {
    __shared__ unsigned s_mn[8], s_mx[8];
    __shared__ unsigned s_red[8];
    __shared__ int s_c1, s_c2, s_c3;
    __shared__ int s_pos;
    __shared__ int   cand[CANDMAX];
    __shared__ float cdv[CANDMAX];

    const int t   = threadIdx.x;
    const int row = blockIdx.x;
    const float* dr = g_d2 + (size_t)row * F;

    // registers: chunk i, elem e -> row index i*1024 + t*4 + e (LDG.128)
    unsigned u[ELEMS];
#pragma unroll
    for (int i = 0; i < 4; ++i) {
        float4 v = *(const float4*)(dr + i * 1024 + t * 4);
        u[i * 4 + 0] = __float_as_uint(fmaxf(v.x, 0.f));
        u[i * 4 + 1] = __float_as_uint(fmaxf(v.y, 0.f));
        u[i * 4 + 2] = __float_as_uint(fmaxf(v.z, 0.f));
        u[i * 4 + 3] = __float_as_uint(fmaxf(v.w, 0.f));
    }

    // --- block min/max of keys ---
    unsigned mn = 0xFFFFFFFFu, mx = 0u;
#pragma unroll
    for (int i = 0; i < ELEMS; ++i) { mn = min(mn, u[i]); mx = max(mx, u[i]); }
    mn = __reduce_min_sync(0xFFFFFFFFu, mn);
    mx = __reduce_max_sync(0xFFFFFFFFu, mx);
    if ((t & 31) == 0) { s_mn[t >> 5] = mn; s_mx[t >> 5] = mx; }
    __syncthreads();
    unsigned lo = s_mn[0], hi = s_mx[0];
#pragma unroll
    for (int j = 1; j < 8; ++j) { lo = min(lo, s_mn[j]); hi = max(hi, s_mx[j]); }

    // --- quaternary bisection: smallest key T with count(u <= T) >= K ---
    // invariants: count(u <= hi) >= K (== chi); count(u <= lo-1) < K.
    int chi = F;
    while (chi > 96 && lo < hi) {
        unsigned span = hi - lo;
        unsigned m1, m2, m3;
        if (span >= 4) {
            m1 = lo + (span >> 2);
            m2 = lo + (span >> 1);
            m3 = hi - (span >> 2);
        } else {
            m1 = lo + (span >> 1); m2 = m1; m3 = m1;
        }
        unsigned pk = 0;   // per-lane counts <=16 each, 10-bit fields
#pragma unroll
        for (int i = 0; i < ELEMS; ++i) {
            pk += (u[i] <= m1) ? 1u : 0u;
            pk += (u[i] <= m2) ? (1u << 10) : 0u;
            pk += (u[i] <= m3) ? (1u << 20) : 0u;
        }
        pk = __reduce_add_sync(0xFFFFFFFFu, pk);   // fields <= 512, no carry
        if ((t & 31) == 0) s_red[t >> 5] = pk;
        __syncthreads();
        if (t == 0) {
            int a = 0, b = 0, c = 0;
#pragma unroll
            for (int j = 0; j < 8; ++j) {
                a += (int)(s_red[j] & 1023u);
                b += (int)((s_red[j] >> 10) & 1023u);
                c += (int)((s_red[j] >> 20) & 1023u);
            }
            s_c1 = a; s_c2 = b; s_c3 = c;
        }
        __syncthreads();
        int c1 = s_c1, c2 = s_c2, c3 = s_c3;
        if (c1 >= K)      { hi = m1; chi = c1; }
        else if (c2 >= K) { lo = m1 + 1; hi = m2; chi = c2; }
        else if (c3 >= K) { lo = m2 + 1; hi = m3; chi = c3; }
        else              { lo = m3 + 1; }
        // next iteration's s_red/s_c* writes are ordered by the two barriers
    }

    // threshold: exact-or-bracketed 16th key, +7 ulp margin (sqrt-round ties)
    unsigned long long t64 = (unsigned long long)hi + 7ull;
    unsigned thr = (t64 > 0xFFFFFFFFull) ? 0xFFFFFFFFu : (unsigned)t64;

    // --- compaction (order arbitrary; ranks are order-independent) ---
    if (t == 0) s_pos = 0;
    __syncthreads();
#pragma unroll
    for (int i = 0; i < ELEMS; ++i) {
        if (u[i] <= thr) {
            int p = atomicAdd_block(&s_pos, 1);
            if (p < CANDMAX) {
                cand[p] = (i >> 2) * 1024 + t * 4 + (i & 3);
                cdv[p]  = sqrtf(__uint_as_float(u[i]));
            }
        }
    }
    __syncthreads();
    int cnt = s_pos < CANDMAX ? s_pos : CANDMAX;

    // --- exact lex (d, idx) ranks in parallel; ranks are a permutation ---
    if (t < cnt) {
        float dq = cdv[t]; int gq = cand[t];
        int rank = 0;
        for (int j = 0; j < cnt; ++j) {
            rank += lexlt(cdv[j], cand[j], dq, gq) ? 1 : 0;
        }
        if (rank < K) g_cols[1 + row * K + rank] = gq;
    }
    if (row == 0 && t == 0) g_cols[0] = 0;
}

// ---------------------------------------------------------------------------
// Kernel 4: gather. RB=4 rows cached in 64 KB smem (the proven store path),
// J loop SPLIT 4-way across CTAs: grid 1024 -> ~3 CTAs/SM resident, enough
// warps to hide the cols-load latency chain.
// ---------------------------------------------------------------------------
#define RB 4
#define SPLIT 4
#define CHUNK ((J + SPLIT - 1) / SPLIT)   // 16385
#define GATHER_SMEM (RB * F * 4)

__global__ __launch_bounds__(256) void k_gather(const float* __restrict__ inputs,
                                                float* __restrict__ out) {
    extern __shared__ float s_in[];   // RB * 4096
    const int group = blockIdx.x >> 2;       // batch group
    const int part  = blockIdx.x & (SPLIT - 1);
    const int b0 = group * RB;

    for (int idx = threadIdx.x; idx < (RB * F) / 4; idx += 256) {
        int r = idx >> 10, q = idx & 1023;
        *(float4*)(s_in + r * F + q * 4) =
            *(const float4*)(inputs + (size_t)(b0 + r) * F + q * 4);
    }
    __syncthreads();

    const int jbeg = part * CHUNK;
    const int jend = (jbeg + CHUNK < J) ? (jbeg + CHUNK) : J;
    for (int j = jbeg + threadIdx.x; j < jend; j += 256) {
        int c = __ldg(&g_cols[j]);
#pragma unroll
        for (int r = 0; r < RB; ++r) {
            __stcs(out + (size_t)(b0 + r) * J + j, s_in[r * F + c]);
        }
    }
}

// ---------------------------------------------------------------------------
extern "C" void kernel_launch(void* const* d_in, const int* in_sizes, int n_in,
                              void* d_out, int out_size) {
    const float* inputs = (const float*)d_in[0];
    const float* coord  = (const float*)d_in[1];
    if (n_in >= 2 && in_sizes[0] < in_sizes[1]) {
        const float* t = inputs; inputs = coord; coord = t;
    }
    float* out = (float*)d_out;

    static bool attr_done = false;
    if (!attr_done) {
        cudaFuncSetAttribute(k_gather, cudaFuncAttributeMaxDynamicSharedMemorySize,
                             GATHER_SMEM);
        attr_done = true;
    }

    k_sq<<<F / 256, 256>>>(coord);
    k_dist<<<(F / ROWS_CTA) * (F / GW), 256>>>(coord);
    k_select<<<F, 256>>>();
    k_gather<<<(B / RB) * SPLIT, 256, GATHER_SMEM>>>(inputs, out);
}

// round 14
// speedup vs baseline: 1.0248x; 1.0248x over previous
#include <cuda_runtime.h>
#include <cstdint>
#include <cfloat>

// Problem constants
#define F 4096      // nb_features
#define C 64        // coord dim
#define B 1024      // batch
#define K 16        // nb_neighbors
#define J (F*K + 1) // 65537 gathered columns

// Scratch (no allocations allowed; __device__ globals are the sanctioned path)
__device__ float g_sq[F];
__device__ int   g_cols[J];
__device__ float g_d2[(size_t)F * F];   // 64 MB distance-squared matrix (L2-resident)

__device__ __forceinline__ bool lexlt(float d, int g, float v, int i) {
    return (d < v) || (d == v && g < i);
}

__device__ __forceinline__ unsigned long long fma2p(unsigned long long a,
                                                    unsigned long long b,
                                                    unsigned long long c) {
    unsigned long long d;
    asm("fma.rn.f32x2 %0, %1, %2, %3;" : "=l"(d) : "l"(a), "l"(b), "l"(c));
    return d;
}
__device__ __forceinline__ float lo32(unsigned long long v) {
    return __uint_as_float((unsigned)v);
}
__device__ __forceinline__ float hi32(unsigned long long v) {
    return __uint_as_float((unsigned)(v >> 32));
}

// ---------------------------------------------------------------------------
// Kernel 1: per-feature squared norms (UNFUSED mul+add, sequential — matches
// the reference's square+reduce rounding; rel_err is exactly 0 with this).
// ---------------------------------------------------------------------------
__global__ __launch_bounds__(256) void k_sq(const float* __restrict__ coord) {
    int f = blockIdx.x * 256 + threadIdx.x;
    float s = 0.f;
#pragma unroll
    for (int c = 0; c < C; ++c) {
        float x = coord[c * F + f];
        s = __fadd_rn(s, __fmul_rn(x, x));
    }
    g_sq[f] = s;
}

// ---------------------------------------------------------------------------
// Kernel 2: PURE distance GEMM -> g_d2 (verified ~52us; FROZEN).
// ---------------------------------------------------------------------------
#define ROWS_CTA 32
#define GW       1024
#define TGG      128
#define NT       (GW / TGG)   // 8

__global__ __launch_bounds__(256) void k_dist(const float* __restrict__ coord) {
    __shared__ float s_f[C * ROWS_CTA];   // 8 KB
    __shared__ float s_sqf[ROWS_CTA];
    __shared__ float s_g[C * TGG];        // 32 KB
    __shared__ float s_sqg[TGG];

    const int tid  = threadIdx.x;
    const int lane = tid & 31;
    const int w    = tid >> 5;           // warp id: rows w*4 .. w*4+3
    const int f0   = (blockIdx.x >> 2) * ROWS_CTA;
    const int g0   = (blockIdx.x & 3) * GW;

    for (int idx = tid; idx < (C * ROWS_CTA) / 4; idx += 256) {
        int c = idx >> 3, r4 = (idx & 7) * 4;
        *(float4*)(s_f + c * ROWS_CTA + r4) = *(const float4*)(coord + c * F + f0 + r4);
    }
    if (tid < ROWS_CTA / 4)
        *(float4*)(s_sqf + tid * 4) = *(const float4*)(g_sq + f0 + tid * 4);

    for (int t = 0; t < NT; ++t) {
        const int gb = g0 + t * TGG;
        __syncthreads();
        for (int idx = tid; idx < (C * TGG) / 4; idx += 256) {
            int c = idx >> 5, o4 = (idx & 31) * 4;
            *(float4*)(s_g + c * TGG + o4) = *(const float4*)(coord + c * F + gb + o4);
        }
        if (tid < TGG / 4)
            *(float4*)(s_sqg + tid * 4) = *(const float4*)(g_sq + gb + tid * 4);
        __syncthreads();

        unsigned long long p00 = 0, p01 = 0, p10 = 0, p11 = 0;
        unsigned long long p20 = 0, p21 = 0, p30 = 0, p31 = 0;

        const float* fp = s_f + w * 4;
        const float* gp = s_g + lane * 4;
#pragma unroll 2
        for (int c = 0; c < C; ++c) {
            float4 a = *(const float4*)(fp + c * ROWS_CTA);            // 4 rows, bcast
            ulonglong2 bb = *(const ulonglong2*)(gp + c * TGG);        // g pairs
            unsigned long long ax, ay, az, aw;
            asm("mov.b64 %0,{%1,%1};" : "=l"(ax) : "r"(__float_as_uint(a.x)));
            asm("mov.b64 %0,{%1,%1};" : "=l"(ay) : "r"(__float_as_uint(a.y)));
            asm("mov.b64 %0,{%1,%1};" : "=l"(az) : "r"(__float_as_uint(a.z)));
            asm("mov.b64 %0,{%1,%1};" : "=l"(aw) : "r"(__float_as_uint(a.w)));
            p00 = fma2p(ax, bb.x, p00);  p01 = fma2p(ax, bb.y, p01);
            p10 = fma2p(ay, bb.x, p10);  p11 = fma2p(ay, bb.y, p11);
            p20 = fma2p(az, bb.x, p20);  p21 = fma2p(az, bb.y, p21);
            p30 = fma2p(aw, bb.x, p30);  p31 = fma2p(aw, bb.y, p31);
        }

        float4 sg = *(const float4*)(s_sqg + lane * 4);
        const float* sfp = s_sqf + w * 4;
        float* obase = g_d2 + (size_t)(f0 + w * 4) * F + gb + lane * 4;
#define FIN_ROW(PL, PH, R)                                                     \
        {                                                                      \
            float sf = sfp[R];                                                 \
            float4 d;                                                          \
            d.x = __fadd_rn(__fmaf_rn(-2.f, lo32(PL), sg.x), sf);              \
            d.y = __fadd_rn(__fmaf_rn(-2.f, hi32(PL), sg.y), sf);              \
            d.z = __fadd_rn(__fmaf_rn(-2.f, lo32(PH), sg.z), sf);              \
            d.w = __fadd_rn(__fmaf_rn(-2.f, hi32(PH), sg.w), sf);              \
            *(float4*)(obase + (size_t)(R) * F) = d;                           \
        }
        FIN_ROW(p00, p01, 0) FIN_ROW(p10, p11, 1)
        FIN_ROW(p20, p21, 2) FIN_ROW(p30, p31, 3)
#undef FIN_ROW
    }
}

// ---------------------------------------------------------------------------
// Kernel 3: per-row top-16 via CTA-wide BINARY bisection on the bit-monotone
// key of fmaxf(d2,0) — exact r12 winner (measured-consistent ~54us).
// One CTA (256 threads) per row.
// ---------------------------------------------------------------------------
#define ELEMS   16              // F / 256
#define CANDMAX 128

__global__ __launch_bounds__(256) void k_select() {
    __shared__ unsigned s_mn[8], s_mx[8];
    __shared__ int s_red[8];
    __shared__ int s_cnt;
    __shared__ int s_pos;
    __shared__ int   cand[CANDMAX];
    __shared__ float cdv[CANDMAX];

    const int t   = threadIdx.x;
    const int row = blockIdx.x;
    const float* dr = g_d2 + (size_t)row * F;

    // registers: element i of thread t is row index i*256 + t (coalesced)
    unsigned u[ELEMS];
#pragma unroll
    for (int i = 0; i < ELEMS; ++i)
        u[i] = __float_as_uint(fmaxf(dr[i * 256 + t], 0.f));

    // --- block min/max of keys ---
    unsigned mn = 0xFFFFFFFFu, mx = 0u;
#pragma unroll
    for (int i = 0; i < ELEMS; ++i) { mn = min(mn, u[i]); mx = max(mx, u[i]); }
    mn = __reduce_min_sync(0xFFFFFFFFu, mn);
    mx = __reduce_max_sync(0xFFFFFFFFu, mx);
    if ((t & 31) == 0) { s_mn[t >> 5] = mn; s_mx[t >> 5] = mx; }
    __syncthreads();
    unsigned lo = s_mn[0], hi = s_mx[0];
#pragma unroll
    for (int j = 1; j < 8; ++j) { lo = min(lo, s_mn[j]); hi = max(hi, s_mx[j]); }

    // --- bisection: smallest key T with count(u <= T) >= K ---
    int chi = F;
    while (chi > 96 && lo < hi) {
        unsigned mid = lo + ((hi - lo) >> 1);
        int lc = 0;
#pragma unroll
        for (int i = 0; i < ELEMS; ++i) lc += (u[i] <= mid) ? 1 : 0;
        lc = __reduce_add_sync(0xFFFFFFFFu, lc);
        if ((t & 31) == 0) s_red[t >> 5] = lc;
        __syncthreads();
        if (t == 0) {
            int c = 0;
#pragma unroll
            for (int j = 0; j < 8; ++j) c += s_red[j];
            s_cnt = c;
        }
        __syncthreads();
        int c = s_cnt;
        if (c >= K) { hi = mid; chi = c; } else { lo = mid + 1; }
    }

    // threshold: exact-or-bracketed 16th key, +7 ulp margin (sqrt-round ties)
    unsigned long long t64 = (unsigned long long)hi + 7ull;
    unsigned thr = (t64 > 0xFFFFFFFFull) ? 0xFFFFFFFFu : (unsigned)t64;

    // --- compaction (order arbitrary; ranks are order-independent) ---
    if (t == 0) s_pos = 0;
    __syncthreads();
#pragma unroll
    for (int i = 0; i < ELEMS; ++i) {
        if (u[i] <= thr) {
            int p = atomicAdd_block(&s_pos, 1);
            if (p < CANDMAX) {
                cand[p] = i * 256 + t;
                cdv[p]  = sqrtf(__uint_as_float(u[i]));
            }
        }
    }
    __syncthreads();
    int cnt = s_pos < CANDMAX ? s_pos : CANDMAX;

    // --- exact lex (d, idx) ranks in parallel; ranks are a permutation ---
    if (t < cnt) {
        float dq = cdv[t]; int gq = cand[t];
        int rank = 0;
        for (int j = 0; j < cnt; ++j) {
            rank += lexlt(cdv[j], cand[j], dq, gq) ? 1 : 0;
        }
        if (rank < K) g_cols[1 + row * K + rank] = gq;
    }
    if (row == 0 && t == 0) g_cols[0] = 0;
}

// ---------------------------------------------------------------------------
// Kernel 4: gather. RB=4 rows in 64 KB smem, grid 256 (one CTA per batch
// group — NO tile re-loading), but 512 threads/CTA: 48 warps/SM resident
// instead of 24, doubling outstanding col-loads/stores. Scalar __stcs path
// (the proven winner).
// ---------------------------------------------------------------------------
#define RB 4
#define GTHREADS 512
#define GATHER_SMEM (RB * F * 4)

__global__ __launch_bounds__(GTHREADS) void k_gather(const float* __restrict__ inputs,
                                                     float* __restrict__ out) {
    extern __shared__ float s_in[];   // RB * 4096
    const int b0 = blockIdx.x * RB;

    for (int idx = threadIdx.x; idx < (RB * F) / 4; idx += GTHREADS) {
        int r = idx >> 10, q = idx & 1023;
        *(float4*)(s_in + r * F + q * 4) =
            *(const float4*)(inputs + (size_t)(b0 + r) * F + q * 4);
    }
    __syncthreads();

#pragma unroll 2
    for (int j = threadIdx.x; j < J; j += GTHREADS) {
        int c = __ldg(&g_cols[j]);
#pragma unroll
        for (int r = 0; r < RB; ++r) {
            __stcs(out + (size_t)(b0 + r) * J + j, s_in[r * F + c]);
        }
    }
}

// ---------------------------------------------------------------------------
extern "C" void kernel_launch(void* const* d_in, const int* in_sizes, int n_in,
                              void* d_out, int out_size) {
    const float* inputs = (const float*)d_in[0];
    const float* coord  = (const float*)d_in[1];
    if (n_in >= 2 && in_sizes[0] < in_sizes[1]) {
        const float* t = inputs; inputs = coord; coord = t;
    }
    float* out = (float*)d_out;

    static bool attr_done = false;
    if (!attr_done) {
        cudaFuncSetAttribute(k_gather, cudaFuncAttributeMaxDynamicSharedMemorySize,
                             GATHER_SMEM);
        attr_done = true;
    }

    k_sq<<<F / 256, 256>>>(coord);
    k_dist<<<(F / ROWS_CTA) * (F / GW), 256>>>(coord);
    k_select<<<F, 256>>>();
    k_gather<<<B / RB, GTHREADS, GATHER_SMEM>>>(inputs, out);
}